// round 8
// baseline (speedup 1.0000x reference)
#include <cuda_runtime.h>

// TTN_Conv_2by2to1: out[n,p,o,x,y] = sum_{c,m} patch[n,c,m,x,y]*W[c,p,x,y,m,o] + bias
// patch m=(ij,kl): ab[ij]*cd[kl] from 2x2 corners of x.
//
// Two-stage contraction per (x,y) block:
//   inner[n,ij,o] = sum_kl cd[n,kl] * w[ij*16+kl, o]   (in registers)
//   out[n,o]     += ab[n,ij] * inner[n,ij,o]
// 128 threads/block, half-warp = one p, lane tile 8n x 6o, packed fp32x2 FMAs.
// Weights staged in NATIVE [m*6+o] layout (straight copy). 64.5 KB smem ->
// 3 CTAs/SM (3 warps/SMSP).

#define NUM   128
#define CIN   3
#define COUT  8
#define NXY   961
#define DOUT  6
#define SX    32
#define SY    32
#define WPP   1536                     // floats per (c,p,xy) weight slice = 256*6

// smem layout (float offsets)
#define W_OFF  0
#define W_SZ   (COUT*WPP)              // 12288 floats (48 KB), no padding
#define AB_ROW 132                     // 128 + pad (16B-aligned rows: 528 B)
#define AB_OFF W_SZ
#define AB_SZ  (16*AB_ROW)             // 2112
#define CD_OFF (AB_OFF+AB_SZ)
#define SMEM_FLOATS (CD_OFF+AB_SZ)     // 16512
#define SMEM_BYTES  (SMEM_FLOATS*4)    // 66048 B -> 3 CTAs/SM

typedef unsigned long long ull;

__device__ __forceinline__ ull pack2(float lo, float hi) {
    ull r; asm("mov.b64 %0, {%1,%2};" : "=l"(r) : "f"(lo), "f"(hi)); return r;
}
__device__ __forceinline__ void unpack2(ull v, float& lo, float& hi) {
    asm("mov.b64 {%0,%1}, %2;" : "=f"(lo), "=f"(hi) : "l"(v));
}
__device__ __forceinline__ void ffma2(ull& d, ull a, ull b) {
    asm("fma.rn.f32x2 %0, %1, %2, %0;" : "+l"(d) : "l"(a), "l"(b));
}

__global__ __launch_bounds__(128, 3)
void ttn_kernel(const float* __restrict__ x,
                const float* __restrict__ w,
                const float* __restrict__ bias,
                float* __restrict__ out)
{
    extern __shared__ float smem[];
    float* w_s  = smem + W_OFF;    // [p][m*6+o], native order
    float* ab_t = smem + AB_OFF;   // [ij][n], row stride AB_ROW
    float* cd_t = smem + CD_OFF;   // [kl][n]

    const int tid  = threadIdx.x;
    const int xy   = blockIdx.x;
    const int Xi   = xy / 31;
    const int Yi   = xy - Xi * 31;
    const int lane = tid & 31;
    const int wid  = tid >> 5;           // 0..3
    const int p    = (wid << 1) | (lane >> 4);   // half-warp -> p (0..7)
    const int n0   = (lane & 15) << 3;   // 8 consecutive n per lane

    ull acc[DOUT][4];
    #pragma unroll
    for (int o = 0; o < DOUT; ++o)
        #pragma unroll
        for (int q = 0; q < 4; ++q) acc[o][q] = 0ULL;

    const int corner = Xi * SY + Yi;

    for (int c = 0; c < CIN; ++c) {
        // ---- stage weights: straight float4 copy into native [p][m*6+o] ----
        {
            const float* wc = w + ((size_t)(c * COUT) * NXY + xy) * WPP;
            const size_t pstride = (size_t)NXY * WPP;
            #pragma unroll
            for (int it = 0; it < 24; ++it) {
                int idx = tid + it * 128;            // 3072 float4 total
                int pp  = idx / 384;                 // 384 float4 per p
                int r   = idx - pp * 384;
                float4 v = __ldg(reinterpret_cast<const float4*>(wc + pp * pstride) + r);
                *reinterpret_cast<float4*>(w_s + pp * WPP + r * 4) = v;
            }
        }
        // ---- ab/cd tables, transposed [ij][n] (one n per thread) ----
        {
            const float* xp = x + ((size_t)(tid * CIN + c) * 4) * (SX * SY) + corner;
            float av[4], bv[4], cv[4], dv[4];
            #pragma unroll
            for (int i = 0; i < 4; ++i) {
                av[i] = __ldg(xp + i * (SX * SY));            // (X  , Y  )
                bv[i] = __ldg(xp + i * (SX * SY) + SY);       // (X+1, Y  )
                cv[i] = __ldg(xp + i * (SX * SY) + 1);        // (X  , Y+1)
                dv[i] = __ldg(xp + i * (SX * SY) + SY + 1);   // (X+1, Y+1)
            }
            #pragma unroll
            for (int i = 0; i < 4; ++i)
                #pragma unroll
                for (int j = 0; j < 4; ++j) {
                    ab_t[(i * 4 + j) * AB_ROW + tid] = av[i] * bv[j];
                    cd_t[(i * 4 + j) * AB_ROW + tid] = cv[i] * dv[j];
                }
        }
        __syncthreads();

        // ---- main: inner kl-contraction in regs, then scale by ab ----
        const float* wp = w_s + p * WPP;
        for (int ij = 0; ij < 16; ++ij) {
            ulonglong2 ab0 = *reinterpret_cast<const ulonglong2*>(ab_t + ij * AB_ROW + n0);
            ulonglong2 ab1 = *reinterpret_cast<const ulonglong2*>(ab_t + ij * AB_ROW + n0 + 4);
            ull abq[4] = {ab0.x, ab0.y, ab1.x, ab1.y};

            ull inner[DOUT][4];
            #pragma unroll
            for (int o = 0; o < DOUT; ++o)
                #pragma unroll
                for (int q = 0; q < 4; ++q) inner[o][q] = 0ULL;

            #pragma unroll
            for (int kl = 0; kl < 16; ++kl) {
                ulonglong2 c0 = *reinterpret_cast<const ulonglong2*>(cd_t + kl * AB_ROW + n0);
                ulonglong2 c1 = *reinterpret_cast<const ulonglong2*>(cd_t + kl * AB_ROW + n0 + 4);
                ull cq[4] = {c0.x, c0.y, c1.x, c1.y};

                const float* wr = wp + ((ij << 4) + kl) * 6;   // 6 w, 8B-aligned
                float2 w01 = *reinterpret_cast<const float2*>(wr);
                float2 w23 = *reinterpret_cast<const float2*>(wr + 2);
                float2 w45 = *reinterpret_cast<const float2*>(wr + 4);
                ull wd[DOUT] = {pack2(w01.x, w01.x), pack2(w01.y, w01.y),
                                pack2(w23.x, w23.x), pack2(w23.y, w23.y),
                                pack2(w45.x, w45.x), pack2(w45.y, w45.y)};
                #pragma unroll
                for (int o = 0; o < DOUT; ++o)
                    #pragma unroll
                    for (int q = 0; q < 4; ++q)
                        ffma2(inner[o][q], cq[q], wd[o]);
            }
            #pragma unroll
            for (int o = 0; o < DOUT; ++o)
                #pragma unroll
                for (int q = 0; q < 4; ++q)
                    ffma2(acc[o][q], inner[o][q], abq[q]);
        }
        __syncthreads();   // protect smem before next c's staging
    }

    // ---- epilogue: bias + store out[n][p][o][xy] ----
    #pragma unroll
    for (int o = 0; o < DOUT; ++o) {
        const float bv = __ldg(bias + ((size_t)p * NXY + xy) * DOUT + o);
        float* ob = out + ((size_t)p * DOUT + o) * NXY + xy;
        #pragma unroll
        for (int q = 0; q < 4; ++q) {
            float lo, hi;
            unpack2(acc[o][q], lo, hi);
            ob[(size_t)(n0 + 2 * q)     * (COUT * DOUT * NXY)] = lo + bv;
            ob[(size_t)(n0 + 2 * q + 1) * (COUT * DOUT * NXY)] = hi + bv;
        }
    }
}

extern "C" void kernel_launch(void* const* d_in, const int* in_sizes, int n_in,
                              void* d_out, int out_size)
{
    const float* x    = (const float*)d_in[0];
    const float* w    = (const float*)d_in[1];
    const float* bias = (const float*)d_in[2];
    float* out = (float*)d_out;

    cudaFuncSetAttribute(ttn_kernel,
                         cudaFuncAttributeMaxDynamicSharedMemorySize, SMEM_BYTES);
    ttn_kernel<<<NXY, 128, SMEM_BYTES>>>(x, w, bias, out);
}

// round 9
// speedup vs baseline: 1.5138x; 1.5138x over previous
#include <cuda_runtime.h>

// TTN_Conv_2by2to1: out[n,p,o,x,y] = sum_{c,m} patch[n,c,m,x,y]*W[c,p,x,y,m,o] + bias
// patch m=(ij,kl): ab[ij]*cd[kl] from the 2x2 corners of x.
//
// One block per (x,y), 256 threads, warp = one p, lane tile 4n x 6o.
// Weights staged PRE-DUPLICATED (w,w) in smem -> broadcast LDS.128 yields
// ready f32x2 multiplicands (no pack instructions in the main loop).
// cd table held in REGISTERS (8 kl at a time) -> main-loop smem traffic is
// 1 ab load per ij + broadcast weight loads only.
// 112 KB smem -> 2 CTAs/SM (4 warps/SMSP), ~95 regs (no spills).

#define NUM   128
#define CIN   3
#define COUT  8
#define NXY   961
#define DOUT  6
#define SX    32
#define SY    32
#define WPP   1536                     // floats per (c,p,xy) weight slice

// smem layout
#define W2_ULL   (COUT*DOUT*256)       // 12288 ull (96 KB), [(p*6+o)*256+m] dup pairs
#define AB_ROW   128                   // floats per row (512 B, conflict-free)
#define AB_OFF   (W2_ULL*2)            // float offset = 24576
#define CD_OFF   (AB_OFF + 16*AB_ROW)  // 26624
#define SMEM_FLOATS (CD_OFF + 16*AB_ROW)   // 28672
#define SMEM_BYTES  (SMEM_FLOATS*4)        // 114688 B (112 KB) -> 2 CTAs/SM

typedef unsigned long long ull;

__device__ __forceinline__ ull pack2(float lo, float hi) {
    ull r; asm("mov.b64 %0, {%1,%2};" : "=l"(r) : "f"(lo), "f"(hi)); return r;
}
__device__ __forceinline__ void unpack2(ull v, float& lo, float& hi) {
    asm("mov.b64 {%0,%1}, %2;" : "=f"(lo), "=f"(hi) : "l"(v));
}
__device__ __forceinline__ ull fmul2(ull a, ull b) {
    ull r; asm("mul.rn.f32x2 %0, %1, %2;" : "=l"(r) : "l"(a), "l"(b)); return r;
}
__device__ __forceinline__ void ffma2(ull& d, ull a, ull b) {
    asm("fma.rn.f32x2 %0, %1, %2, %0;" : "+l"(d) : "l"(a), "l"(b));
}

__global__ __launch_bounds__(256, 2)
void ttn_kernel(const float* __restrict__ x,
                const float* __restrict__ w,
                const float* __restrict__ bias,
                float* __restrict__ out)
{
    extern __shared__ float smem[];
    ull*   w2_s = reinterpret_cast<ull*>(smem);   // [(p*6+o)*256+m] = (w,w)
    float* ab_t = smem + AB_OFF;                  // [ij][n], row 128
    float* cd_t = smem + CD_OFF;                  // [kl][n]

    const int tid  = threadIdx.x;
    const int xy   = blockIdx.x;
    const int Xi   = xy / 31;
    const int Yi   = xy - Xi * 31;
    const int lane = tid & 31;
    const int p    = tid >> 5;        // warp id = output channel p (0..7)
    const int n0   = lane << 2;       // 4 consecutive n per lane (covers 128)

    ull acc[DOUT][2];
    #pragma unroll
    for (int o = 0; o < DOUT; ++o) { acc[o][0] = 0ULL; acc[o][1] = 0ULL; }

    const int corner = Xi * SY + Yi;

    for (int c = 0; c < CIN; ++c) {
        // ---- stage weights DUPLICATED: w2[(p*6+o)*256+m] = (v,v) ----
        {
            const float* wc = w + ((size_t)(c * COUT) * NXY + xy) * WPP;
            const size_t pstride = (size_t)NXY * WPP;
            #pragma unroll
            for (int it = 0; it < 12; ++it) {
                int idx = tid + it * 256;            // 3072 float4 total
                int pp  = idx / 384;                 // 384 float4 per p
                int r   = idx - pp * 384;
                float4 v = __ldg(reinterpret_cast<const float4*>(wc + pp * pstride) + r);
                int t = r * 4;                       // element = m*6+o
                float vv[4] = {v.x, v.y, v.z, v.w};
                #pragma unroll
                for (int e = 0; e < 4; ++e) {
                    int tt = t + e;
                    int mI = tt / 6;
                    int oI = tt - mI * 6;
                    w2_s[(pp * DOUT + oI) * 256 + mI] = pack2(vv[e], vv[e]);
                }
            }
        }
        // ---- ab/cd tables, transposed [ij][n] (threads 0..127, one n each) ----
        if (tid < NUM) {
            const float* xp = x + ((size_t)(tid * CIN + c) * 4) * (SX * SY) + corner;
            float av[4], bv[4], cv[4], dv[4];
            #pragma unroll
            for (int i = 0; i < 4; ++i) {
                av[i] = __ldg(xp + i * (SX * SY));            // (X  , Y  )
                bv[i] = __ldg(xp + i * (SX * SY) + SY);       // (X+1, Y  )
                cv[i] = __ldg(xp + i * (SX * SY) + 1);        // (X  , Y+1)
                dv[i] = __ldg(xp + i * (SX * SY) + SY + 1);   // (X+1, Y+1)
            }
            #pragma unroll
            for (int i = 0; i < 4; ++i)
                #pragma unroll
                for (int j = 0; j < 4; ++j) {
                    ab_t[(i * 4 + j) * AB_ROW + tid] = av[i] * bv[j];
                    cd_t[(i * 4 + j) * AB_ROW + tid] = cv[i] * dv[j];
                }
        }
        __syncthreads();

        // ---- main loop: cd in registers (8 kl per half), broadcast weights ----
        const ull* wp = w2_s + p * DOUT * 256;
        #pragma unroll
        for (int half = 0; half < 2; ++half) {
            // load this half's cd rows into registers: 8 kl x (2 ull = 4 n)
            ulonglong2 cq[8];
            #pragma unroll
            for (int k = 0; k < 8; ++k)
                cq[k] = *reinterpret_cast<const ulonglong2*>(
                    cd_t + (half * 8 + k) * AB_ROW + n0);

            for (int ij = 0; ij < 16; ++ij) {
                ulonglong2 ab = *reinterpret_cast<const ulonglong2*>(
                    ab_t + ij * AB_ROW + n0);
                const int mbase = (ij << 4) + (half << 3);

                #pragma unroll
                for (int klp = 0; klp < 4; ++klp) {
                    const int m0 = mbase + klp * 2;
                    // patch for kl0,kl1 (2 fmul2 each): reused across 6 o
                    ull pa0 = fmul2(ab.x, cq[klp * 2].x);
                    ull pa1 = fmul2(ab.y, cq[klp * 2].y);
                    ull pb0 = fmul2(ab.x, cq[klp * 2 + 1].x);
                    ull pb1 = fmul2(ab.y, cq[klp * 2 + 1].y);
                    #pragma unroll
                    for (int o = 0; o < DOUT; ++o) {
                        // broadcast LDS.128: dup pairs for (m0, m0+1)
                        ulonglong2 wv = *reinterpret_cast<const ulonglong2*>(
                            wp + (o << 8) + m0);
                        ffma2(acc[o][0], pa0, wv.x);
                        ffma2(acc[o][1], pa1, wv.x);
                        ffma2(acc[o][0], pb0, wv.y);
                        ffma2(acc[o][1], pb1, wv.y);
                    }
                }
            }
        }
        __syncthreads();   // protect smem before next c's staging
    }

    // ---- epilogue: bias + store out[n][p][o][xy] ----
    #pragma unroll
    for (int o = 0; o < DOUT; ++o) {
        const float bv = __ldg(bias + ((size_t)p * NXY + xy) * DOUT + o);
        float* ob = out + ((size_t)p * DOUT + o) * NXY + xy;
        #pragma unroll
        for (int q = 0; q < 2; ++q) {
            float lo, hi;
            unpack2(acc[o][q], lo, hi);
            ob[(size_t)(n0 + 2 * q)     * (COUT * DOUT * NXY)] = lo + bv;
            ob[(size_t)(n0 + 2 * q + 1) * (COUT * DOUT * NXY)] = hi + bv;
        }
    }
}

extern "C" void kernel_launch(void* const* d_in, const int* in_sizes, int n_in,
                              void* d_out, int out_size)
{
    const float* x    = (const float*)d_in[0];
    const float* w    = (const float*)d_in[1];
    const float* bias = (const float*)d_in[2];
    float* out = (float*)d_out;

    cudaFuncSetAttribute(ttn_kernel,
                         cudaFuncAttributeMaxDynamicSharedMemorySize, SMEM_BYTES);
    ttn_kernel<<<NXY, 256, SMEM_BYTES>>>(x, w, bias, out);
}

// round 12
// speedup vs baseline: 1.5507x; 1.0244x over previous
#include <cuda_runtime.h>

// TTN_Conv_2by2to1: out[n,p,o,x,y] = sum_{c,m} patch[n,c,m,x,y]*W[c,p,x,y,m,o] + bias
// patch m=(ij,kl): ab[ij]*cd[kl] from the 2x2 corners of x.
//
// One block per (x,y), 256 threads, warp = one p, lane tile 4n x 6o.
// f32x2 packing is over the o axis: acc[n][(o,o+1)], so the weight operand is
// the NATIVE [m][o0..o5] row (three 16B-aligned ull pairs, broadcast LDS, no
// packs, no transpose; staging is a straight float4 copy). The per-n patch
// operand is lane-duplicated, built from PRE-DUPLICATED ab/cd tables (32 KB).
// cd lives in registers by 4-kl quarters. 80 KB smem -> 2 CTAs/SM.

#define NUM   128
#define CIN   3
#define COUT  8
#define NXY   961
#define DOUT  6
#define SX    32
#define SY    32
#define WPP   1536                    // floats per (c,p,xy) weight slice

// smem: [0, 12288) floats = native weights (48 KB);
//       then ab_d (2048 ull, 16 KB), cd_d (2048 ull, 16 KB)
#define W_FLOATS 12288
#define SMEM_BYTES (W_FLOATS*4 + 2*2048*8)   // 81920 B

typedef unsigned long long ull;

__device__ __forceinline__ ull pack2(float lo, float hi) {
    ull r; asm("mov.b64 %0, {%1,%2};" : "=l"(r) : "f"(lo), "f"(hi)); return r;
}
__device__ __forceinline__ void unpack2(ull v, float& lo, float& hi) {
    asm("mov.b64 {%0,%1}, %2;" : "=f"(lo), "=f"(hi) : "l"(v));
}
__device__ __forceinline__ ull fmul2(ull a, ull b) {
    ull r; asm("mul.rn.f32x2 %0, %1, %2;" : "=l"(r) : "l"(a), "l"(b)); return r;
}
__device__ __forceinline__ void ffma2(ull& d, ull a, ull b) {
    asm("fma.rn.f32x2 %0, %1, %2, %0;" : "+l"(d) : "l"(a), "l"(b));
}

__global__ __launch_bounds__(256, 2)
void ttn_kernel(const float* __restrict__ x,
                const float* __restrict__ w,
                const float* __restrict__ bias,
                float* __restrict__ out)
{
    extern __shared__ float smem[];
    float* w_s  = smem;                                   // [p][m*6+o] native
    ull*   ab_d = reinterpret_cast<ull*>(smem + W_FLOATS);// [ij][n] dup pairs
    ull*   cd_d = ab_d + 2048;                            // [kl][n] dup pairs

    const int tid  = threadIdx.x;
    const int xy   = blockIdx.x;
    const int Xi   = xy / 31;
    const int Yi   = xy - Xi * 31;
    const int lane = tid & 31;
    const int p    = tid >> 5;        // warp id = output channel p (0..7)
    const int n0   = lane << 2;       // 4 consecutive n per lane

    // acc[n][opair]: opair 0 -> (o0,o1), 1 -> (o2,o3), 2 -> (o4,o5)
    ull acc[4][3];
    #pragma unroll
    for (int n = 0; n < 4; ++n)
        #pragma unroll
        for (int op = 0; op < 3; ++op) acc[n][op] = 0ULL;

    const int corner = Xi * SY + Yi;

    for (int c = 0; c < CIN; ++c) {
        // ---- stage weights: straight float4 copy, native layout ----
        {
            const float* wc = w + ((size_t)(c * COUT) * NXY + xy) * WPP;
            const size_t pstride = (size_t)NXY * WPP;
            #pragma unroll
            for (int it = 0; it < 12; ++it) {
                int idx = tid + it * 256;          // 3072 float4 total
                int pp  = idx / 384;               // 384 float4 per p
                int r   = idx - pp * 384;
                float4 v = __ldg(reinterpret_cast<const float4*>(wc + pp * pstride) + r);
                *reinterpret_cast<float4*>(w_s + pp * WPP + r * 4) = v;
            }
        }
        // ---- duplicated ab/cd tables: threads 0-127 build ab, 128-255 cd ----
        {
            const int  tb    = tid & 127;          // n index
            const bool doCd  = (tid >= 128);
            const int  off1  = doCd ? 1 : 0;       // (X,Y) vs (X,Y+1) column
            const float* xp  = x + ((size_t)(tb * CIN + c) * 4) * (SX * SY)
                                 + corner + off1;
            float u[4], v[4];
            #pragma unroll
            for (int i = 0; i < 4; ++i) {
                u[i] = __ldg(xp + i * (SX * SY));        // a_i  or c_i
                v[i] = __ldg(xp + i * (SX * SY) + SY);   // b_i  or d_i
            }
            ull* tab = doCd ? cd_d : ab_d;
            #pragma unroll
            for (int i = 0; i < 4; ++i)
                #pragma unroll
                for (int j = 0; j < 4; ++j) {
                    float prod = u[i] * v[j];
                    tab[(i * 4 + j) * 128 + tb] = pack2(prod, prod);
                }
        }
        __syncthreads();

        // ---- main loop: cd in regs by quarters, native weight ull pairs ----
        const float* wp  = w_s + p * WPP;
        const ull*   abp = ab_d + n0;
        const ull*   cdp = cd_d + n0;
        for (int q4 = 0; q4 < 4; ++q4) {
            ulonglong2 cdA[4], cdB[4];             // [k]: n0..n0+1, n0+2..n0+3
            #pragma unroll
            for (int k = 0; k < 4; ++k) {
                const ull* r = cdp + (q4 * 4 + k) * 128;
                cdA[k] = *reinterpret_cast<const ulonglong2*>(r);
                cdB[k] = *reinterpret_cast<const ulonglong2*>(r + 2);
            }
            for (int ij = 0; ij < 16; ++ij) {
                const ull* ar = abp + ij * 128;
                ulonglong2 abA = *reinterpret_cast<const ulonglong2*>(ar);
                ulonglong2 abB = *reinterpret_cast<const ulonglong2*>(ar + 2);
                const int mbase = ij * 16 + q4 * 4;
                #pragma unroll
                for (int kp = 0; kp < 2; ++kp) {
                    const int m0 = mbase + kp * 2;        // even
                    const ulonglong2* wr =
                        reinterpret_cast<const ulonglong2*>(wp + m0 * 6);
                    ulonglong2 wA = wr[0];   // m0:(o0,o1) (o2,o3)
                    ulonglong2 wB = wr[1];   // m0:(o4,o5)  m1:(o0,o1)
                    ulonglong2 wC = wr[2];   // m1:(o2,o3) (o4,o5)
                    // kl = kp*2  (weights of m0)
                    {
                        ull p0 = fmul2(abA.x, cdA[kp * 2].x);
                        ull p1 = fmul2(abA.y, cdA[kp * 2].y);
                        ull p2 = fmul2(abB.x, cdB[kp * 2].x);
                        ull p3 = fmul2(abB.y, cdB[kp * 2].y);
                        ffma2(acc[0][0], p0, wA.x); ffma2(acc[0][1], p0, wA.y); ffma2(acc[0][2], p0, wB.x);
                        ffma2(acc[1][0], p1, wA.x); ffma2(acc[1][1], p1, wA.y); ffma2(acc[1][2], p1, wB.x);
                        ffma2(acc[2][0], p2, wA.x); ffma2(acc[2][1], p2, wA.y); ffma2(acc[2][2], p2, wB.x);
                        ffma2(acc[3][0], p3, wA.x); ffma2(acc[3][1], p3, wA.y); ffma2(acc[3][2], p3, wB.x);
                    }
                    // kl = kp*2+1  (weights of m0+1)
                    {
                        ull p0 = fmul2(abA.x, cdA[kp * 2 + 1].x);
                        ull p1 = fmul2(abA.y, cdA[kp * 2 + 1].y);
                        ull p2 = fmul2(abB.x, cdB[kp * 2 + 1].x);
                        ull p3 = fmul2(abB.y, cdB[kp * 2 + 1].y);
                        ffma2(acc[0][0], p0, wB.y); ffma2(acc[0][1], p0, wC.x); ffma2(acc[0][2], p0, wC.y);
                        ffma2(acc[1][0], p1, wB.y); ffma2(acc[1][1], p1, wC.x); ffma2(acc[1][2], p1, wC.y);
                        ffma2(acc[2][0], p2, wB.y); ffma2(acc[2][1], p2, wC.x); ffma2(acc[2][2], p2, wC.y);
                        ffma2(acc[3][0], p3, wB.y); ffma2(acc[3][1], p3, wC.x); ffma2(acc[3][2], p3, wC.y);
                    }
                }
            }
        }
        __syncthreads();   // protect smem before next c's staging
    }

    // ---- epilogue: bias + store out[n][p][o][xy] ----
    float bv[DOUT];
    #pragma unroll
    for (int o = 0; o < DOUT; ++o)
        bv[o] = __ldg(bias + ((size_t)p * NXY + xy) * DOUT + o);

    #pragma unroll
    for (int n = 0; n < 4; ++n) {
        const size_t nb = (size_t)(n0 + n) * (COUT * DOUT * NXY)
                        + (size_t)p * (DOUT * NXY) + xy;
        #pragma unroll
        for (int op = 0; op < 3; ++op) {
            float lo, hi;
            unpack2(acc[n][op], lo, hi);
            out[nb + (size_t)(2 * op)     * NXY] = lo + bv[2 * op];
            out[nb + (size_t)(2 * op + 1) * NXY] = hi + bv[2 * op + 1];
        }
    }
}

extern "C" void kernel_launch(void* const* d_in, const int* in_sizes, int n_in,
                              void* d_out, int out_size)
{
    const float* x    = (const float*)d_in[0];
    const float* w    = (const float*)d_in[1];
    const float* bias = (const float*)d_in[2];
    float* out = (float*)d_out;

    cudaFuncSetAttribute(ttn_kernel,
                         cudaFuncAttributeMaxDynamicSharedMemorySize, SMEM_BYTES);
    ttn_kernel<<<NXY, 256, SMEM_BYTES>>>(x, w, bias, out);
}